// round 4
// baseline (speedup 1.0000x reference)
#include <cuda_runtime.h>
#include <cuda_bf16.h>

#define NN 16384
#define TI 256      // rows per block in main kernel
#define TJ 1024     // cols per block in main kernel

// ---------------- device scratch (no allocations allowed) ----------------
__device__ float              g_s[NN];       // scores sorted by rank (counting sort)
__device__ int                g_hist[NN];    // rank histogram
__device__ int                g_start[NN];   // exclusive prefix of hist
__device__ int                g_off[NN];     // scatter cursors (consumed)
__device__ int                g_is32;        // 1 if ranks buffer is int32, 0 if int64
__device__ double             g_total;       // upper-triangle hinge sum
__device__ double             g_tie_loss;    // correction: hinge over tied pairs
__device__ unsigned long long g_tie_cnt;     // number of tied unordered pairs

// ---------------- f32x2 packed helpers (sm_100a) ----------------
__device__ __forceinline__ unsigned long long f32x2_add(unsigned long long a,
                                                        unsigned long long b) {
    unsigned long long r;
    asm("add.rn.f32x2 %0, %1, %2;" : "=l"(r) : "l"(a), "l"(b));
    return r;
}
__device__ __forceinline__ unsigned long long relu2(unsigned long long t) {
    float lo, hi;
    asm("mov.b64 {%0, %1}, %2;" : "=f"(lo), "=f"(hi) : "l"(t));
    lo = fmaxf(lo, 0.0f);
    hi = fmaxf(hi, 0.0f);
    unsigned long long r;
    asm("mov.b64 %0, {%1, %2};" : "=l"(r) : "f"(lo), "f"(hi));
    return r;
}
__device__ __forceinline__ unsigned long long pack_dup(float a) {
    unsigned long long r;
    asm("mov.b64 %0, {%1, %1};" : "=l"(r) : "f"(a));
    return r;
}

// ---------------- setup kernels ----------------
__global__ void k_init() {
    int i = blockIdx.x * blockDim.x + threadIdx.x;
    if (i < NN) g_hist[i] = 0;
    if (i == 0) { g_total = 0.0; g_tie_loss = 0.0; g_tie_cnt = 0ull; g_is32 = 0; }
}

// Decide ranks dtype by inspecting odd 32-bit words of the FIRST 64KB
// (always in-bounds for both int32[NN] and int64[NN]).
//   int64 (LE): odd words are high halves of values in [0, 2^15) -> all zero.
//   int32:      odd words are actual rank values -> essentially never all zero.
__global__ void k_detect(const unsigned int* __restrict__ w) {
    int i = blockIdx.x * blockDim.x + threadIdx.x;   // i in [0, NN/2)
    if (i < NN / 2 && w[2 * i + 1] != 0u) g_is32 = 1;
}

// Low 32-bit word of element i holds the full rank value in both dtypes.
__device__ __forceinline__ int load_rank(const int* w, int i) {
    int r = w[g_is32 ? i : 2 * i];
    if ((unsigned)r >= (unsigned)NN) r = 0;   // defensive clamp: never IMA
    return r;
}

__global__ void k_hist(const int* __restrict__ ranks_w) {
    int i = blockIdx.x * blockDim.x + threadIdx.x;
    if (i < NN) atomicAdd(&g_hist[load_rank(ranks_w, i)], 1);
}

// single block, 1024 threads, each owns 16 consecutive bins
__global__ void k_scan() {
    __shared__ int part[1024];
    int tid = threadIdx.x;
    int base = tid * 16;
    int loc[16];
    int s = 0;
#pragma unroll
    for (int k = 0; k < 16; k++) { loc[k] = s; s += g_hist[base + k]; }
    part[tid] = s;
    int own = s;
    __syncthreads();
    for (int d = 1; d < 1024; d <<= 1) {
        int add = (tid >= d) ? part[tid - d] : 0;
        __syncthreads();
        part[tid] += add;
        __syncthreads();
    }
    int excl = part[tid] - own;
#pragma unroll
    for (int k = 0; k < 16; k++) {
        int v = excl + loc[k];
        g_start[base + k] = v;
        g_off[base + k]   = v;
    }
}

__global__ void k_scatter(const float* __restrict__ scores,
                          const int* __restrict__ ranks_w) {
    int i = blockIdx.x * blockDim.x + threadIdx.x;
    if (i < NN) {
        int r = load_rank(ranks_w, i);
        int pos = atomicAdd(&g_off[r], 1);
        if ((unsigned)pos < (unsigned)NN) g_s[pos] = scores[i];
    }
}

// one thread per rank value: correct for tied pairs inside each run.
// Must compute the hinge EXACTLY as the main kernel does (fp32, ap = 1-s_p)
// so the subtraction cancels the main kernel's contribution for tied pairs.
__global__ void k_tie() {
    int v = blockIdx.x * blockDim.x + threadIdx.x;
    if (v >= NN) return;
    int c = g_hist[v];
    if (c >= 2) {
        int st = g_start[v];
        double tl = 0.0;
        for (int q = 1; q < c; q++) {
            float sq = g_s[st + q];
            for (int p = 0; p < q; p++) {
                float ap = 1.0f - g_s[st + p];
                tl += (double)fmaxf(ap + sq, 0.0f);
            }
        }
        atomicAdd(&g_tie_loss, tl);
        atomicAdd(&g_tie_cnt, (unsigned long long)(c * (c - 1) / 2));
    }
}

// ---------------- main O(N^2/2) kernel ----------------
// grid (NN/TJ, NN/TI); block handles rows [a*TI, a*TI+TI) x cols [b*TJ, b*TJ+TJ)
// Sum over positions p<q of relu((1 - s_p) + s_q).
__global__ void __launch_bounds__(TI) k_main() {
    __shared__ __align__(16) float scol[TJ];
    int a = blockIdx.y, b = blockIdx.x;
    int rowStart = a * TI;
    int colStart = b * TJ;
    if (colStart + TJ - 1 <= rowStart) return;  // entire tile has q <= p

    for (int t = threadIdx.x; t < TJ; t += TI)
        scol[t] = g_s[colStart + t];
    __syncthreads();

    int p = rowStart + threadIdx.x;
    float ap = 1.0f - g_s[p];
    float sumf;

    if (colStart >= rowStart + TI) {
        // fast path: all q > p, packed f32x2
        unsigned long long a2 = pack_dup(ap);
        unsigned long long acc0 = 0ull, acc1 = 0ull, acc2 = 0ull, acc3 = 0ull;
        const ulonglong2* wp = (const ulonglong2*)scol;
#pragma unroll 4
        for (int j = 0; j < TJ / 4; j += 2) {
            ulonglong2 w0 = wp[j];
            ulonglong2 w1 = wp[j + 1];
            acc0 = f32x2_add(acc0, relu2(f32x2_add(w0.x, a2)));
            acc1 = f32x2_add(acc1, relu2(f32x2_add(w0.y, a2)));
            acc2 = f32x2_add(acc2, relu2(f32x2_add(w1.x, a2)));
            acc3 = f32x2_add(acc3, relu2(f32x2_add(w1.y, a2)));
        }
        float l0, h0, l1, h1, l2, h2, l3, h3;
        asm("mov.b64 {%0, %1}, %2;" : "=f"(l0), "=f"(h0) : "l"(acc0));
        asm("mov.b64 {%0, %1}, %2;" : "=f"(l1), "=f"(h1) : "l"(acc1));
        asm("mov.b64 {%0, %1}, %2;" : "=f"(l2), "=f"(h2) : "l"(acc2));
        asm("mov.b64 {%0, %1}, %2;" : "=f"(l3), "=f"(h3) : "l"(acc3));
        sumf = ((l0 + h0) + (l1 + h1)) + ((l2 + h2) + (l3 + h3));
    } else {
        // diagonal-crossing tile: mask q > p
        sumf = 0.0f;
        for (int j = 0; j < TJ; j++) {
            int q = colStart + j;
            if (q > p) sumf += fmaxf(ap + scol[j], 0.0f);
        }
    }

    // block reduction -> one double atomicAdd per block
    unsigned mask = 0xffffffffu;
    float v = sumf;
    for (int o = 16; o; o >>= 1) v += __shfl_down_sync(mask, v, o);
    __shared__ float wsum[TI / 32];
    int lane = threadIdx.x & 31, wid = threadIdx.x >> 5;
    if (lane == 0) wsum[wid] = v;
    __syncthreads();
    if (threadIdx.x == 0) {
        float s = 0.0f;
#pragma unroll
        for (int k = 0; k < TI / 32; k++) s += wsum[k];
        atomicAdd(&g_total, (double)s);
    }
}

__global__ void k_final(float* out) {
    long long np = (long long)NN * (NN - 1) / 2 - (long long)g_tie_cnt;
    double t = g_total - g_tie_loss;
    out[0] = (np > 0) ? (float)(t / (double)np) : 0.0f;
}

// ---------------- launch ----------------
extern "C" void kernel_launch(void* const* d_in, const int* in_sizes, int n_in,
                              void* d_out, int out_size) {
    const float* scores  = (const float*)d_in[0];
    const void*  ranks   = d_in[1];
    float* out = (float*)d_out;

    k_init   <<<NN / 256, 256>>>();
    k_detect <<<NN / 512, 256>>>((const unsigned int*)ranks);
    k_hist   <<<NN / 256, 256>>>((const int*)ranks);
    k_scan   <<<1, 1024>>>();
    k_scatter<<<NN / 256, 256>>>(scores, (const int*)ranks);
    k_tie    <<<NN / 256, 256>>>();
    k_main   <<<dim3(NN / TJ, NN / TI), TI>>>();
    k_final  <<<1, 1>>>(out);
}

// round 5
// speedup vs baseline: 1.9472x; 1.9472x over previous
#include <cuda_runtime.h>
#include <cuda_bf16.h>

#define NN 16384
#define C  256          // position-block size
#define NB (NN / C)     // 64 blocks
#define GX (NB + 2)     // fused-main grid.x: 64 cross cols + diag + tie
#define NPART (GX * NB)

// ---------------- device scratch ----------------
__device__ __align__(16) float g_s[NN];        // scores sorted by rank
__device__ __align__(16) int   g_hist[NN];
__device__ __align__(16) int   g_start[NN];
__device__ __align__(16) int   g_off[NN];
__device__ __align__(16) float g_sorted[NN];   // per 256-block value-sorted
__device__ __align__(16) float g_ssum[NN];     // per 256-block suffix sums
__device__ int                 g_det[NB];      // per-block int32-detect votes
__device__ unsigned long long  g_tie_cnt;
__device__ double              g_part[NPART];  // per-block partial sums

// ---------------- K1: init + dtype detect ----------------
// grid 64 x 256. Zeros hist & partials; votes g_det[b] = OR of odd words of
// the first 64KB of ranks (int64 -> all high halves zero; int32 -> values).
__global__ void k_init(const unsigned int* __restrict__ w) {
    int i = blockIdx.x * 256 + threadIdx.x;        // 0..16383
    g_hist[i] = 0;
    if (i < NPART) g_part[i] = 0.0;
    int found = (i < NN / 2) ? (w[2 * i + 1] != 0u) : 0;
    int any = __syncthreads_or(found);
    if (threadIdx.x == 0) g_det[blockIdx.x] = any;
}

__device__ __forceinline__ int block_is32(int tid) {
    __shared__ int s_is32;
    if (tid == 0) {
        int o = 0;
#pragma unroll
        for (int k = 0; k < NB; k++) o |= g_det[k];
        s_is32 = o;
    }
    __syncthreads();
    return s_is32;
}

__device__ __forceinline__ int load_rank(const int* w, int i, int is32) {
    int r = w[is32 ? i : 2 * i];
    if ((unsigned)r >= (unsigned)NN) r = 0;   // defensive: never IMA
    return r;
}

// ---------------- K2: histogram ----------------
__global__ void k_hist(const int* __restrict__ rw) {
    int tid = threadIdx.x;
    int is32 = block_is32(tid);
    int i = blockIdx.x * 256 + tid;
    atomicAdd(&g_hist[load_rank(rw, i, is32)], 1);
}

// ---------------- K3: scan (1 block, 1024 threads, register-resident) ----
// Also computes g_tie_cnt = sum C(c,2).
__global__ void k_scan() {
    const int tid = threadIdx.x, lane = tid & 31, wid = tid >> 5;
    const int4* h4 = (const int4*)g_hist;
    int4 a = h4[tid * 4 + 0], b = h4[tid * 4 + 1];
    int4 c = h4[tid * 4 + 2], d = h4[tid * 4 + 3];
    int s = a.x + a.y + a.z + a.w + b.x + b.y + b.z + b.w +
            c.x + c.y + c.z + c.w + d.x + d.y + d.z + d.w;

    // warp inclusive scan of per-thread sums
    int incl = s;
#pragma unroll
    for (int o = 1; o < 32; o <<= 1) {
        int n = __shfl_up_sync(0xffffffffu, incl, o);
        if (lane >= o) incl += n;
    }
    __shared__ int wtot[32], wbase[32];
    if (lane == 31) wtot[wid] = incl;
    __syncthreads();
    if (wid == 0) {
        int v = wtot[lane];
        int wi = v;
#pragma unroll
        for (int o = 1; o < 32; o <<= 1) {
            int n = __shfl_up_sync(0xffffffffu, wi, o);
            if (lane >= o) wi += n;
        }
        wbase[lane] = wi - v;   // exclusive
    }
    __syncthreads();
    int run = wbase[wid] + incl - s;   // exclusive base for this thread's 16 bins

    int4 o4;
    o4.x = run; run += a.x; o4.y = run; run += a.y; o4.z = run; run += a.z; o4.w = run; run += a.w;
    ((int4*)g_start)[tid * 4 + 0] = o4; ((int4*)g_off)[tid * 4 + 0] = o4;
    o4.x = run; run += b.x; o4.y = run; run += b.y; o4.z = run; run += b.z; o4.w = run; run += b.w;
    ((int4*)g_start)[tid * 4 + 1] = o4; ((int4*)g_off)[tid * 4 + 1] = o4;
    o4.x = run; run += c.x; o4.y = run; run += c.y; o4.z = run; run += c.z; o4.w = run; run += c.w;
    ((int4*)g_start)[tid * 4 + 2] = o4; ((int4*)g_off)[tid * 4 + 2] = o4;
    o4.x = run; run += d.x; o4.y = run; run += d.y; o4.z = run; run += d.z; o4.w = run; run += d.w;
    ((int4*)g_start)[tid * 4 + 3] = o4; ((int4*)g_off)[tid * 4 + 3] = o4;

    // tie pair count
    long long tc =
        (long long)a.x*(a.x-1)/2 + (long long)a.y*(a.y-1)/2 + (long long)a.z*(a.z-1)/2 + (long long)a.w*(a.w-1)/2 +
        (long long)b.x*(b.x-1)/2 + (long long)b.y*(b.y-1)/2 + (long long)b.z*(b.z-1)/2 + (long long)b.w*(b.w-1)/2 +
        (long long)c.x*(c.x-1)/2 + (long long)c.y*(c.y-1)/2 + (long long)c.z*(c.z-1)/2 + (long long)c.w*(c.w-1)/2 +
        (long long)d.x*(d.x-1)/2 + (long long)d.y*(d.y-1)/2 + (long long)d.z*(d.z-1)/2 + (long long)d.w*(d.w-1)/2;
#pragma unroll
    for (int o = 16; o; o >>= 1) tc += __shfl_down_sync(0xffffffffu, tc, o);
    __shared__ long long wt[32];
    if (lane == 0) wt[wid] = tc;
    __syncthreads();
    if (tid == 0) {
        long long t = 0;
#pragma unroll
        for (int k = 0; k < 32; k++) t += wt[k];
        g_tie_cnt = (unsigned long long)t;
    }
}

// ---------------- K4: scatter (counting-sort placement) ----------------
__global__ void k_scatter(const float* __restrict__ scores,
                          const int* __restrict__ rw) {
    int tid = threadIdx.x;
    int is32 = block_is32(tid);
    int i = blockIdx.x * 256 + tid;
    int r = load_rank(rw, i, is32);
    int pos = atomicAdd(&g_off[r], 1);
    if ((unsigned)pos < (unsigned)NN) g_s[pos] = scores[i];
}

// ---------------- K5: per-block bitonic sort + suffix sums ----------------
__global__ void __launch_bounds__(C) k_sort() {
    __shared__ float v[C];
    __shared__ float ss[C];
    int tid = threadIdx.x, b = blockIdx.x;
    v[tid] = g_s[b * C + tid];
    __syncthreads();
    for (int k = 2; k <= C; k <<= 1)
        for (int j = k >> 1; j > 0; j >>= 1) {
            int ixj = tid ^ j;
            if (ixj > tid) {
                float x = v[tid], y = v[ixj];
                bool up = ((tid & k) == 0);
                if ((x > y) == up) { v[tid] = y; v[ixj] = x; }
            }
            __syncthreads();
        }
    ss[tid] = v[tid];
    __syncthreads();
    for (int off = 1; off < C; off <<= 1) {
        float add = (tid + off < C) ? ss[tid + off] : 0.0f;
        __syncthreads();
        ss[tid] += add;
        __syncthreads();
    }
    g_sorted[b * C + tid] = v[tid];
    g_ssum[b * C + tid] = ss[tid];
}

// ---------------- block reduction -> partial slot ----------------
__device__ __forceinline__ void block_store_partial(double v, int slot, int tid) {
#pragma unroll
    for (int o = 16; o; o >>= 1) v += __shfl_down_sync(0xffffffffu, v, o);
    __shared__ double wsd[8];
    int lane = tid & 31, wid = tid >> 5;
    if (lane == 0) wsd[wid] = v;
    __syncthreads();
    if (tid == 0) {
        double s = 0.0;
#pragma unroll
        for (int k = 0; k < 8; k++) s += wsd[k];
        g_part[slot] = s;
    }
}

// ---------------- K6: fused main: cross (analytic) + diag + tie ----------
// grid (GX=66, 64), 256 threads.
//  x <  64 : cross block-pair (row-block r=y, col-block c=x), active iff c>r
//  x == 64 : diagonal triangle of block y (brute force)
//  x == 65 : tie correction for rank bins [256y, 256y+256)
__global__ void __launch_bounds__(C) k_mainf() {
    int tid = threadIdx.x;
    int x = blockIdx.x, y = blockIdx.y;
    int slot = y * GX + x;

    if (x < NB) {
        int r = y, c = x;
        if (c <= r) return;                 // uniform early exit, slot stays 0
        __shared__ float sc[C];
        __shared__ float sm[C + 1];
        sc[tid] = g_sorted[c * C + tid];
        sm[tid] = g_ssum[c * C + tid];
        if (tid == 0) sm[C] = 0.0f;
        __syncthreads();
        float ap = 1.0f - g_s[r * C + tid];
        float t = -ap;
        int lo = 0, hi = C;
        while (lo < hi) {                   // first idx with sc[idx] > t
            int m = (lo + hi) >> 1;
            if (sc[m] > t) hi = m; else lo = m + 1;
        }
        float contrib = fmaf((float)(C - lo), ap, sm[lo]);
        block_store_partial((double)contrib, slot, tid);
    } else if (x == NB) {
        __shared__ float sd[C];
        sd[tid] = g_s[y * C + tid];
        __syncthreads();
        float ap = 1.0f - sd[tid];
        float sum = 0.0f;
        for (int j = tid + 1; j < C; j++) sum += fmaxf(ap + sd[j], 0.0f);
        block_store_partial((double)sum, slot, tid);
    } else {
        int v = y * C + tid;
        int cnt = g_hist[v];
        double tl = 0.0;
        if (cnt >= 2) {
            int st = g_start[v];
            for (int q = 1; q < cnt; q++) {
                float sq = g_s[st + q];
                for (int p = 0; p < q; p++)
                    tl += (double)fmaxf((1.0f - g_s[st + p]) + sq, 0.0f);
            }
        }
        block_store_partial(-tl, slot, tid);
    }
}

// ---------------- K7: final reduction ----------------
__global__ void k_final(float* out) {
    __shared__ double smm[256];
    int tid = threadIdx.x;
    double s = 0.0;
    for (int i = tid; i < NPART; i += 256) s += g_part[i];
    smm[tid] = s;
    __syncthreads();
    for (int o = 128; o; o >>= 1) {
        if (tid < o) smm[tid] += smm[tid + o];
        __syncthreads();
    }
    if (tid == 0) {
        double np = (double)((long long)NN * (NN - 1) / 2 - (long long)g_tie_cnt);
        out[0] = (np > 0.0) ? (float)(smm[0] / np) : 0.0f;
    }
}

// ---------------- launch ----------------
extern "C" void kernel_launch(void* const* d_in, const int* in_sizes, int n_in,
                              void* d_out, int out_size) {
    const float* scores = (const float*)d_in[0];
    const void*  ranks  = d_in[1];
    float* out = (float*)d_out;

    k_init   <<<NB, 256>>>((const unsigned int*)ranks);
    k_hist   <<<NB, 256>>>((const int*)ranks);
    k_scan   <<<1, 1024>>>();
    k_scatter<<<NB, 256>>>(scores, (const int*)ranks);
    k_sort   <<<NB, C>>>();
    k_mainf  <<<dim3(GX, NB), C>>>();
    k_final  <<<1, 256>>>(out);
}